// round 1
// baseline (speedup 1.0000x reference)
#include <cuda_runtime.h>
#include <math.h>

#define TOKENS 65536
#define DDIM   512
#define NEXP   8
#define HDIM   2048
#define CAP    65536          // per-expert worst-case token capacity

// ---------------- scratch (no allocs allowed -> __device__ globals) ----------
__device__ int   g_counts [NEXP];
__device__ int   g_offsets[NEXP];
__device__ int   g_tokens [NEXP * CAP];
__device__ float g_gates  [NEXP * CAP];
// compacted hidden activations: 2*TOKENS rows x HDIM  (= 1 GiB)
__device__ float g_hbuf[(size_t)2 * TOKENS * HDIM];

// ---------------- small utility kernels -------------------------------------
__global__ void zero_counts_kernel() {
    if (threadIdx.x < NEXP) g_counts[threadIdx.x] = 0;
}

__global__ void offsets_kernel() {
    if (threadIdx.x == 0) {
        int s = 0;
        #pragma unroll
        for (int e = 0; e < NEXP; e++) { g_offsets[e] = s; s += g_counts[e]; }
    }
}

// ---------------- router: logits -> top2 -> renorm softmax -> gather lists ---
__global__ void router_kernel(const float* __restrict__ x,
                              const float* __restrict__ rw,
                              const float* __restrict__ rb) {
    __shared__ float srw[DDIM * NEXP];           // 16 KB
    int tid = threadIdx.x;
    for (int i = tid; i < DDIM * NEXP; i += blockDim.x) srw[i] = rw[i];
    __syncthreads();

    int warp = tid >> 5, lane = tid & 31;
    int t = blockIdx.x * 8 + warp;               // 8 warps/block, warp per token
    const float* xr = x + (size_t)t * DDIM;

    float acc[NEXP];
    #pragma unroll
    for (int e = 0; e < NEXP; e++) acc[e] = 0.f;
    for (int d = lane; d < DDIM; d += 32) {
        float xv = xr[d];
        #pragma unroll
        for (int e = 0; e < NEXP; e++) acc[e] += xv * srw[d * NEXP + e];
    }
    #pragma unroll
    for (int e = 0; e < NEXP; e++) {
        #pragma unroll
        for (int o = 16; o > 0; o >>= 1)
            acc[e] += __shfl_xor_sync(0xffffffffu, acc[e], o);
    }

    if (lane == 0) {
        float l[NEXP];
        #pragma unroll
        for (int e = 0; e < NEXP; e++) l[e] = acc[e] + rb[e];
        // top-1 (first occurrence on tie, matching lax.top_k)
        int e1 = 0;
        #pragma unroll
        for (int e = 1; e < NEXP; e++) if (l[e] > l[e1]) e1 = e;
        // top-2 excluding e1
        int e2 = (e1 == 0) ? 1 : 0;
        #pragma unroll
        for (int e = 0; e < NEXP; e++)
            if (e != e1 && l[e] > l[e2]) e2 = e;
        // renormalized top-2 softmax weights
        float d2 = expf(l[e2] - l[e1]);
        float g2 = d2 / (1.f + d2);
        float g1 = 1.f - g2;

        int p1 = atomicAdd(&g_counts[e1], 1);
        g_tokens[e1 * CAP + p1] = t;  g_gates[e1 * CAP + p1] = g1;
        int p2 = atomicAdd(&g_counts[e2], 1);
        g_tokens[e2 * CAP + p2] = t;  g_gates[e2 * CAP + p2] = g2;
    }
}

// ---------------- SGEMM tiles -------------------------------------------------
#define BM  128
#define BN  128
#define BKK 16
#define AP  132   // smem pitch (floats), 16B-aligned, bank-stagger
#define BP  132

// GEMM1: h = relu( gather(x) @ w1[e] + b1[e] )   M=count[e], N=2048, K=512
__global__ __launch_bounds__(256, 2)
void gemm1_kernel(const float* __restrict__ x,
                  const float* __restrict__ w1,
                  const float* __restrict__ b1) {
    int e   = blockIdx.z;
    int cnt = g_counts[e];
    int m0  = blockIdx.y * BM;
    if (m0 >= cnt) return;
    int n0  = blockIdx.x * BN;
    int off = g_offsets[e];
    const float* Bw = w1 + (size_t)e * DDIM * HDIM;

    __shared__ float As[BKK * AP];
    __shared__ float Bs[BKK * BP];

    int tid = threadIdx.x;
    // A-load mapping: 2 float4 rows per thread (rows tid/4 and tid/4+64)
    int arow0 = tid >> 2;
    int arow1 = arow0 + 64;
    int acg   = (tid & 3) * 4;  // k-offset within BK tile
    int mr0 = m0 + arow0; if (mr0 > cnt - 1) mr0 = cnt - 1;
    int mr1 = m0 + arow1; if (mr1 > cnt - 1) mr1 = cnt - 1;
    const float* a0p = x + (size_t)g_tokens[e * CAP + mr0] * DDIM + acg;
    const float* a1p = x + (size_t)g_tokens[e * CAP + mr1] * DDIM + acg;

    // B-load mapping: rows tid/32 and tid/32+8, one float4 each
    int brow = tid >> 5;
    int bc   = (tid & 31) * 4;
    const float* b0p = Bw + (size_t)brow * HDIM + n0 + bc;
    const float* b1p = b0p + (size_t)8 * HDIM;

    int tx = tid & 15, ty = tid >> 4;
    float c[8][8];
    #pragma unroll
    for (int i = 0; i < 8; i++)
        #pragma unroll
        for (int j = 0; j < 8; j++) c[i][j] = 0.f;

    for (int k0 = 0; k0 < DDIM; k0 += BKK) {
        float4 av0 = *(const float4*)(a0p + k0);
        float4 av1 = *(const float4*)(a1p + k0);
        float4 bv0 = *(const float4*)(b0p + (size_t)k0 * HDIM);
        float4 bv1 = *(const float4*)(b1p + (size_t)k0 * HDIM);
        __syncthreads();
        As[(acg + 0) * AP + arow0] = av0.x;
        As[(acg + 1) * AP + arow0] = av0.y;
        As[(acg + 2) * AP + arow0] = av0.z;
        As[(acg + 3) * AP + arow0] = av0.w;
        As[(acg + 0) * AP + arow1] = av1.x;
        As[(acg + 1) * AP + arow1] = av1.y;
        As[(acg + 2) * AP + arow1] = av1.z;
        As[(acg + 3) * AP + arow1] = av1.w;
        *(float4*)&Bs[brow * BP + bc]       = bv0;
        *(float4*)&Bs[(brow + 8) * BP + bc] = bv1;
        __syncthreads();
        #pragma unroll
        for (int k = 0; k < BKK; k++) {
            float4 aA = *(const float4*)&As[k * AP + ty * 8];
            float4 aB = *(const float4*)&As[k * AP + ty * 8 + 4];
            float4 bA = *(const float4*)&Bs[k * BP + tx * 8];
            float4 bB = *(const float4*)&Bs[k * BP + tx * 8 + 4];
            float a[8] = {aA.x, aA.y, aA.z, aA.w, aB.x, aB.y, aB.z, aB.w};
            float b[8] = {bA.x, bA.y, bA.z, bA.w, bB.x, bB.y, bB.z, bB.w};
            #pragma unroll
            for (int i = 0; i < 8; i++)
                #pragma unroll
                for (int j = 0; j < 8; j++) c[i][j] += a[i] * b[j];
        }
    }

    // epilogue: bias + relu, store to compacted h buffer
    float bias[8];
    #pragma unroll
    for (int j = 0; j < 8; j++) bias[j] = b1[(size_t)e * HDIM + n0 + tx * 8 + j];
    #pragma unroll
    for (int i = 0; i < 8; i++) {
        int m = m0 + ty * 8 + i;
        if (m < cnt) {
            float* hr = g_hbuf + (size_t)(off + m) * HDIM + n0 + tx * 8;
            float4 v0, v1;
            v0.x = fmaxf(c[i][0] + bias[0], 0.f);
            v0.y = fmaxf(c[i][1] + bias[1], 0.f);
            v0.z = fmaxf(c[i][2] + bias[2], 0.f);
            v0.w = fmaxf(c[i][3] + bias[3], 0.f);
            v1.x = fmaxf(c[i][4] + bias[4], 0.f);
            v1.y = fmaxf(c[i][5] + bias[5], 0.f);
            v1.z = fmaxf(c[i][6] + bias[6], 0.f);
            v1.w = fmaxf(c[i][7] + bias[7], 0.f);
            *(float4*)(hr)     = v0;
            *(float4*)(hr + 4) = v1;
        }
    }
}

// GEMM2: out[token] += gate * ( h @ w2[e] + b2[e] )   M=count[e], N=512, K=2048
__global__ __launch_bounds__(256, 2)
void gemm2_kernel(const float* __restrict__ w2,
                  const float* __restrict__ b2,
                  float* __restrict__ out) {
    int e   = blockIdx.z;
    int cnt = g_counts[e];
    int m0  = blockIdx.y * BM;
    if (m0 >= cnt) return;
    int n0  = blockIdx.x * BN;
    int off = g_offsets[e];
    const float* Bw = w2 + (size_t)e * HDIM * DDIM;

    __shared__ float As[BKK * AP];
    __shared__ float Bs[BKK * BP];

    int tid = threadIdx.x;
    int arow0 = tid >> 2;
    int arow1 = arow0 + 64;
    int acg   = (tid & 3) * 4;
    int mr0 = m0 + arow0; if (mr0 > cnt - 1) mr0 = cnt - 1;
    int mr1 = m0 + arow1; if (mr1 > cnt - 1) mr1 = cnt - 1;
    const float* a0p = g_hbuf + (size_t)(off + mr0) * HDIM + acg;
    const float* a1p = g_hbuf + (size_t)(off + mr1) * HDIM + acg;

    int brow = tid >> 5;
    int bc   = (tid & 31) * 4;
    const float* b0p = Bw + (size_t)brow * DDIM + n0 + bc;
    const float* b1p = b0p + (size_t)8 * DDIM;

    int tx = tid & 15, ty = tid >> 4;
    float c[8][8];
    #pragma unroll
    for (int i = 0; i < 8; i++)
        #pragma unroll
        for (int j = 0; j < 8; j++) c[i][j] = 0.f;

    for (int k0 = 0; k0 < HDIM; k0 += BKK) {
        float4 av0 = *(const float4*)(a0p + k0);
        float4 av1 = *(const float4*)(a1p + k0);
        float4 bv0 = *(const float4*)(b0p + (size_t)k0 * DDIM);
        float4 bv1 = *(const float4*)(b1p + (size_t)k0 * DDIM);
        __syncthreads();
        As[(acg + 0) * AP + arow0] = av0.x;
        As[(acg + 1) * AP + arow0] = av0.y;
        As[(acg + 2) * AP + arow0] = av0.z;
        As[(acg + 3) * AP + arow0] = av0.w;
        As[(acg + 0) * AP + arow1] = av1.x;
        As[(acg + 1) * AP + arow1] = av1.y;
        As[(acg + 2) * AP + arow1] = av1.z;
        As[(acg + 3) * AP + arow1] = av1.w;
        *(float4*)&Bs[brow * BP + bc]       = bv0;
        *(float4*)&Bs[(brow + 8) * BP + bc] = bv1;
        __syncthreads();
        #pragma unroll
        for (int k = 0; k < BKK; k++) {
            float4 aA = *(const float4*)&As[k * AP + ty * 8];
            float4 aB = *(const float4*)&As[k * AP + ty * 8 + 4];
            float4 bA = *(const float4*)&Bs[k * BP + tx * 8];
            float4 bB = *(const float4*)&Bs[k * BP + tx * 8 + 4];
            float a[8] = {aA.x, aA.y, aA.z, aA.w, aB.x, aB.y, aB.z, aB.w};
            float b[8] = {bA.x, bA.y, bA.z, bA.w, bB.x, bB.y, bB.z, bB.w};
            #pragma unroll
            for (int i = 0; i < 8; i++)
                #pragma unroll
                for (int j = 0; j < 8; j++) c[i][j] += a[i] * b[j];
        }
    }

    // epilogue: gate-scale, bias, scatter-add into out (2 commutative adds/token)
    float bias[8];
    #pragma unroll
    for (int j = 0; j < 8; j++) bias[j] = b2[(size_t)e * DDIM + n0 + tx * 8 + j];
    #pragma unroll
    for (int i = 0; i < 8; i++) {
        int m = m0 + ty * 8 + i;
        if (m < cnt) {
            int   tok  = g_tokens[e * CAP + m];
            float gate = g_gates[e * CAP + m];
            float* orow = out + (size_t)tok * DDIM + n0 + tx * 8;
            #pragma unroll
            for (int j = 0; j < 8; j++)
                atomicAdd(&orow[j], gate * (c[i][j] + bias[j]));
        }
    }
}

// ---------------- launch ------------------------------------------------------
extern "C" void kernel_launch(void* const* d_in, const int* in_sizes, int n_in,
                              void* d_out, int out_size) {
    const float* x   = (const float*)d_in[0];   // [65536,512]
    const float* rw  = (const float*)d_in[1];   // [512,8]
    const float* rb  = (const float*)d_in[2];   // [8]
    const float* w1  = (const float*)d_in[3];   // [8,512,2048]
    const float* b1  = (const float*)d_in[4];   // [8,2048]
    const float* w2  = (const float*)d_in[5];   // [8,2048,512]
    const float* b2  = (const float*)d_in[6];   // [8,512]
    float*       out = (float*)d_out;           // [65536,512]

    cudaMemsetAsync(out, 0, (size_t)out_size * sizeof(float));
    zero_counts_kernel<<<1, 32>>>();
    router_kernel<<<TOKENS / 8, 256>>>(x, rw, rb);
    offsets_kernel<<<1, 32>>>();

    dim3 g1(HDIM / BN, (CAP + BM - 1) / BM, NEXP);   // (16, 512, 8)
    gemm1_kernel<<<g1, 256>>>(x, w1, b1);

    dim3 g2(DDIM / BN, (CAP + BM - 1) / BM, NEXP);   // (4, 512, 8)
    gemm2_kernel<<<g2, 256>>>(w2, b2, out);
}